// round 11
// baseline (speedup 1.0000x reference)
#include <cuda_runtime.h>
#include <cuda_fp16.h>

// WeightedDiceLoss (sm_103a) — 4 small CTAs/SM, swizzled fp16 hsum ring,
// local 3-lane hsum producer, prefetch-pipelined refills.
// weight = 1 + 5*|boxavg31(target) - target|, zero pad, /961
// out = 1 - (2*sum(in*t*w) + 1) / (sum(in*w) + sum(t*w) + 1)

#define Wd    512
#define Hd    512
#define Rr    64
#define HALO  15
#define SLABR (Rr + 2*HALO)        // 94
#define RING  48                   // fp16 rows of 1KB -> 48KB
#define INV_KK2 (1.0f/961.0f)

__device__ float g_part[3 * 1024];
__device__ unsigned int g_count = 0;

__global__ __launch_bounds__(256, 4)
void wdice_main(const float* __restrict__ input,
                const float* __restrict__ target,
                float* __restrict__ out)
{
    extern __shared__ __half HS[];          // [RING][512] swizzled fp16 hsum
    __shared__ float red[24];
    __shared__ unsigned int sIsLast;

    const int tid  = threadIdx.x;
    const int wid  = tid >> 5;              // 0..7
    const int lane = tid & 31;
    const int img  = blockIdx.x >> 3;       // 8 slabs/image
    const int slab = blockIdx.x & 7;
    const int r0   = slab * Rr;
    const size_t imgOff = (size_t)img * (size_t)(Hd * Wd);

    // LDG target row (r0-15+pr+wid) into regs (zeros if outside image).
    auto pref = [&](int pr, float v[16]) {
        const int j  = pr + wid;            // 8 rows per call
        const int gr = r0 - HALO + j;
        if (j < SLABR && gr >= 0 && gr < Hd) {
            const float4* row = (const float4*)(target + imgOff + (size_t)gr * Wd);
            #pragma unroll
            for (int q = 0; q < 4; q++) {
                float4 f = row[lane * 4 + q];
                v[4*q+0] = f.x; v[4*q+1] = f.y; v[4*q+2] = f.z; v[4*q+3] = f.w;
            }
        } else {
            #pragma unroll
            for (int i = 0; i < 16; i++) v[i] = 0.f;
        }
    };

    // Local-prefix hsum (window spans <=3 lanes) -> fp16 -> swizzled STS.128.
    auto scanStore = [&](int pr, float p[16]) {
        const int j = pr + wid;
        if (j >= SLABR) return;
        #pragma unroll
        for (int i = 1; i < 16; i++) p[i] += p[i-1];
        const float T  = p[15];
        float Tp = __shfl_up_sync(0xffffffffu, T, 1);
        if (lane == 0) Tp = 0.f;
        const float base = Tp + T;
        float h[16];
        #pragma unroll
        for (int i = 0; i < 16; i++) {
            float pm = __shfl_up_sync(0xffffffffu, p[i], 1);
            if (lane == 0) pm = 0.f;
            h[i] = base - pm;
        }
        #pragma unroll
        for (int i = 1; i < 16; i++) {
            float pp = __shfl_down_sync(0xffffffffu, p[i-1], 1);
            if (lane == 31) pp = 0.f;
            h[i] += pp;
        }
        unsigned up[8];
        #pragma unroll
        for (int q = 0; q < 8; q++) {
            __half2 hh = __floats2half2_rn(h[2*q], h[2*q+1]);
            up[q] = *reinterpret_cast<unsigned*>(&hh);
        }
        uint4* dstRow = (uint4*)((char*)HS + (size_t)(j % RING) * 1024);
        const int key = (lane >> 2) & 7;    // = (u>>3)&7 for u = 2*lane{,+1}
        dstRow[(2 * lane)     ^ key] = make_uint4(up[0], up[1], up[2], up[3]);
        dstRow[(2 * lane + 1) ^ key] = make_uint4(up[4], up[5], up[6], up[7]);
    };

    // ---- Priming rows 0..47 with pipelined prefetch; pw ends holding rows 48..55.
    float pw[16];
    {
        float pa[16];
        pref(0,  pw); pref(8,  pa);
        scanStore(0,  pw); pref(16, pw);
        scanStore(8,  pa); pref(24, pa);
        scanStore(16, pw); pref(32, pw);
        scanStore(24, pa); pref(40, pa);
        scanStore(32, pw); pref(48, pw);
        scanStore(40, pa);
    }
    __syncthreads();

    // ---- Consumer: thread owns column pair (2ct, 2ct+1).
    const int ct = tid;
    const int u  = ct >> 2;
    const int pu = u ^ ((u >> 3) & 7);
    const int qoff = pu * 16 + (ct & 3) * 4;       // swizzled byte offset in row
    const char* HSb = (const char*)HS;

    float2 vs = make_float2(0.f, 0.f);
    #pragma unroll
    for (int j = 0; j <= 2 * HALO; j++) {
        float2 a = __half22float2(*(const __half2*)(HSb + j * 1024 + qoff));
        vs.x += a.x; vs.y += a.y;
    }

    float2 aI = make_float2(0.f, 0.f);
    float2 aA = make_float2(0.f, 0.f);
    float2 aB = make_float2(0.f, 0.f);
    const float2* tgt = (const float2*)(target + imgOff + (size_t)r0 * Wd) + ct;
    const float2* inp = (const float2*)(input  + imgOff + (size_t)r0 * Wd) + ct;

    #pragma unroll
    for (int ch = 0; ch < 8; ch++) {               // 8 chunks x 8 rows
        #pragma unroll
        for (int kk = 0; kk < 8; kk++) {
            const int k = ch * 8 + kk;
            const float2 t2 = tgt[k * 256];
            const float2 i2 = inp[k * 256];
            const float w0 = fmaf(5.f, fabsf(fmaf(vs.x, INV_KK2, -t2.x)), 1.f);
            const float w1 = fmaf(5.f, fabsf(fmaf(vs.y, INV_KK2, -t2.y)), 1.f);
            const float tw0 = t2.x * w0, tw1 = t2.y * w1;
            aI.x = fmaf(i2.x, tw0, aI.x);  aI.y = fmaf(i2.y, tw1, aI.y);
            aA.x = fmaf(i2.x, w0,  aA.x);  aA.y = fmaf(i2.y, w1,  aA.y);
            aB.x += tw0;                   aB.y += tw1;

            if (k < Rr - 1) {
                const int ja = (k + 31) % RING;
                const int js = k % RING;
                float2 a = __half22float2(*(const __half2*)(HSb + ja * 1024 + qoff));
                float2 s = __half22float2(*(const __half2*)(HSb + js * 1024 + qoff));
                vs.x += a.x - s.x;
                vs.y += a.y - s.y;
            }
        }
        __syncthreads();                    // rows ch*8..+7 dead
        if (ch < 7) {
            scanStore(48 + ch * 8, pw);     // LDG issued one chunk ago
            if (ch < 6) pref(56 + ch * 8, pw);
            __syncthreads();
        }
    }

    float rI = aI.x + aI.y, rA = aA.x + aA.y, rB = aB.x + aB.y;

    // ---- Block reduction (fixed order -> deterministic)
    #pragma unroll
    for (int o = 16; o > 0; o >>= 1) {
        rI += __shfl_down_sync(0xffffffffu, rI, o);
        rA += __shfl_down_sync(0xffffffffu, rA, o);
        rB += __shfl_down_sync(0xffffffffu, rB, o);
    }
    if (lane == 0) { red[wid] = rI; red[8 + wid] = rA; red[16 + wid] = rB; }
    __syncthreads();
    if (tid == 0) {
        float I = 0.f, A = 0.f, B = 0.f;
        #pragma unroll
        for (int i = 0; i < 8; i++) { I += red[i]; A += red[8 + i]; B += red[16 + i]; }
        g_part[blockIdx.x * 3 + 0] = I;
        g_part[blockIdx.x * 3 + 1] = A;
        g_part[blockIdx.x * 3 + 2] = B;
        __threadfence();
        sIsLast = (atomicAdd(&g_count, 1u) == gridDim.x - 1u);
    }
    __syncthreads();

    if (sIsLast) {
        const int nb = gridDim.x;
        float i = 0.f, a = 0.f, b = 0.f;
        for (int j = tid; j < nb; j += 256) {
            i += g_part[3 * j + 0];
            a += g_part[3 * j + 1];
            b += g_part[3 * j + 2];
        }
        #pragma unroll
        for (int o = 16; o > 0; o >>= 1) {
            i += __shfl_down_sync(0xffffffffu, i, o);
            a += __shfl_down_sync(0xffffffffu, a, o);
            b += __shfl_down_sync(0xffffffffu, b, o);
        }
        __syncthreads();
        if (lane == 0) { red[wid] = i; red[8 + wid] = a; red[16 + wid] = b; }
        __syncthreads();
        if (tid == 0) {
            float I = 0.f, A = 0.f, B = 0.f;
            #pragma unroll
            for (int q = 0; q < 8; q++) { I += red[q]; A += red[8 + q]; B += red[16 + q]; }
            out[0] = 1.f - (2.f * I + 1.f) / (A + B + 1.f);
            g_count = 0;
        }
    }
}

extern "C" void kernel_launch(void* const* d_in, const int* in_sizes, int n_in,
                              void* d_out, int out_size)
{
    const float* input  = (const float*)d_in[0];
    const float* target = (const float*)d_in[1];
    const int nImg = in_sizes[0] / (Hd * Wd);
    const int grid = nImg * (Hd / Rr);              // 512
    const size_t smem = (size_t)RING * Wd * sizeof(__half);   // 49152 B

    cudaFuncSetAttribute(wdice_main,
                         cudaFuncAttributeMaxDynamicSharedMemorySize, (int)smem);
    wdice_main<<<grid, 256, smem>>>(input, target, (float*)d_out);
}

// round 12
// speedup vs baseline: 1.3299x; 1.3299x over previous
#include <cuda_runtime.h>
#include <cuda_fp16.h>

// WeightedDiceLoss (sm_103a) — fp16 swizzled ring RING=64, ONE barrier per
// chunk (2-chunk RAW slack), local 3-lane hsum producer, prefetch pipelining.
// weight = 1 + 5*|boxavg31(target) - target|, zero pad, /961
// out = 1 - (2*sum(in*t*w) + 1) / (sum(in*w) + sum(t*w) + 1)

#define Wd    512
#define Hd    512
#define Rr    128
#define HALO  15
#define SLABR (Rr + 2*HALO)        // 158
#define RING  64                   // fp16 rows of 1KB -> 64KB
#define NCHUNK (Rr / 16)           // 8
#define INV_KK2 (1.0f/961.0f)

__device__ float g_part[3 * 1024];
__device__ unsigned int g_count = 0;

__global__ __launch_bounds__(512, 2)
void wdice_main(const float* __restrict__ input,
                const float* __restrict__ target,
                float* __restrict__ out)
{
    extern __shared__ __half HS[];          // [RING][512] swizzled fp16 hsum
    const int tid  = threadIdx.x;
    const int wid  = tid >> 5;
    const int lane = tid & 31;
    const int img  = blockIdx.x >> 2;       // 4 slabs per image
    const int slab = blockIdx.x & 3;
    const int r0   = slab * Rr;
    const size_t imgOff = (size_t)img * (size_t)(Hd * Wd);

    // LDG target row (r0-15+pr+wid) into regs (zeros if outside image).
    auto pref = [&](int pr, float v[16]) {
        const int j  = pr + wid;            // 16 rows per call
        const int gr = r0 - HALO + j;
        if (j < SLABR && gr >= 0 && gr < Hd) {
            const float4* row = (const float4*)(target + imgOff + (size_t)gr * Wd);
            #pragma unroll
            for (int q = 0; q < 4; q++) {
                float4 f = row[lane * 4 + q];
                v[4*q+0] = f.x; v[4*q+1] = f.y; v[4*q+2] = f.z; v[4*q+3] = f.w;
            }
        } else {
            #pragma unroll
            for (int i = 0; i < 16; i++) v[i] = 0.f;
        }
    };

    // Local-prefix hsum (window spans <=3 lanes) -> fp16 -> swizzled STS.128.
    //   hsum[16L+i] = (T_{L-1} - p_{L-1}[i]) + T_L + p_{L+1}[i-1]
    auto scanStore = [&](int pr, float p[16]) {
        const int j = pr + wid;
        if (j >= SLABR) return;
        #pragma unroll
        for (int i = 1; i < 16; i++) p[i] += p[i-1];
        const float T  = p[15];
        float Tp = __shfl_up_sync(0xffffffffu, T, 1);
        if (lane == 0) Tp = 0.f;
        const float base = Tp + T;
        float h[16];
        #pragma unroll
        for (int i = 0; i < 16; i++) {
            float pm = __shfl_up_sync(0xffffffffu, p[i], 1);
            if (lane == 0) pm = 0.f;
            h[i] = base - pm;
        }
        #pragma unroll
        for (int i = 1; i < 16; i++) {
            float pp = __shfl_down_sync(0xffffffffu, p[i-1], 1);
            if (lane == 31) pp = 0.f;
            h[i] += pp;
        }
        unsigned up[8];
        #pragma unroll
        for (int q = 0; q < 8; q++) {
            __half2 hh = __floats2half2_rn(h[2*q], h[2*q+1]);
            up[q] = *reinterpret_cast<unsigned*>(&hh);
        }
        // lane owns 16B units u0=2L, u1=2L+1 of a 64-unit row; swizzle key (u>>3)&7
        uint4* dstRow = (uint4*)((char*)HS + (size_t)(j & (RING - 1)) * 1024);
        const int key = (lane >> 2) & 7;
        dstRow[(2 * lane)     ^ key] = make_uint4(up[0], up[1], up[2], up[3]);
        dstRow[(2 * lane + 1) ^ key] = make_uint4(up[4], up[5], up[6], up[7]);
    };

    // ---- Priming: rows 0..63 with two-buffer LDG/scan overlap; pw ends
    // holding rows 64..79 (first refill).
    float pw[16];
    {
        float pa[16];
        pref(0,  pa); pref(16, pw);
        scanStore(0, pa);  pref(32, pa);
        scanStore(16, pw); pref(48, pw);
        scanStore(32, pa);
        scanStore(48, pw);
        pref(64, pw);
    }
    __syncthreads();

    // ---- Consumer: thread = column c (fixed swizzled byte offset).
    const int c = tid;
    const int u = c >> 3;                          // 16B unit (8 halfs)
    const int qoff = (u ^ ((u >> 3) & 7)) * 16 + (c & 7) * 2;
    const char* HSb = (const char*)HS;

    float vsum = 0.f;
    #pragma unroll
    for (int j = 0; j <= 2 * HALO; j++)
        vsum += __half2float(*(const __half*)(HSb + j * 1024 + qoff));

    float aI = 0.f, aA = 0.f, aB = 0.f;
    const float* inp = input  + imgOff + (size_t)r0 * Wd + c;
    const float* tgt = target + imgOff + (size_t)r0 * Wd + c;

    #pragma unroll
    for (int ch = 0; ch < NCHUNK; ch++) {
        #pragma unroll
        for (int kk = 0; kk < 16; kk++) {
            const int k = ch * 16 + kk;
            const float t  = tgt[k * Wd];
            const float in = inp[k * Wd];
            const float w  = fmaf(5.f, fabsf(fmaf(vsum, INV_KK2, -t)), 1.f);
            const float tw = t * w;
            aI = fmaf(in, tw, aI);
            aA = fmaf(in, w,  aA);
            aB += tw;

            if (k < Rr - 1) {
                const int ja = (k + 31) & (RING - 1);
                const int js = k & (RING - 1);
                const float a = __half2float(*(const __half*)(HSb + ja * 1024 + qoff));
                const float s = __half2float(*(const __half*)(HSb + js * 1024 + qoff));
                vsum += (a - s);
            }
        }
        __syncthreads();                    // single barrier per chunk
        if (ch < NCHUNK - 1) {
            scanStore(64 + ch * 16, pw);    // LDG issued one chunk ago
            if (ch < NCHUNK - 2)
                pref(80 + ch * 16, pw);     // hides behind next consume
        }
        // no second barrier: produce(ch)'s rows are first read by
        // consume(ch+2), which is separated by the next chunk's barrier.
    }

    // ---- Block reduction (fixed order -> deterministic)
    #pragma unroll
    for (int o = 16; o > 0; o >>= 1) {
        aI += __shfl_down_sync(0xffffffffu, aI, o);
        aA += __shfl_down_sync(0xffffffffu, aA, o);
        aB += __shfl_down_sync(0xffffffffu, aB, o);
    }
    __syncthreads();                        // ring dead; reuse as float scratch
    float* red = (float*)HS;
    if (lane == 0) { red[wid] = aI; red[16 + wid] = aA; red[32 + wid] = aB; }
    __syncthreads();
    __shared__ unsigned int sIsLast;
    if (tid == 0) {
        float I = 0.f, A = 0.f, B = 0.f;
        #pragma unroll
        for (int i = 0; i < 16; i++) { I += red[i]; A += red[16 + i]; B += red[32 + i]; }
        g_part[blockIdx.x * 3 + 0] = I;
        g_part[blockIdx.x * 3 + 1] = A;
        g_part[blockIdx.x * 3 + 2] = B;
        __threadfence();
        sIsLast = (atomicAdd(&g_count, 1u) == gridDim.x - 1u);
    }
    __syncthreads();

    if (sIsLast) {
        const int nb = gridDim.x;
        float i = 0.f, a = 0.f, b = 0.f;
        for (int j = tid; j < nb; j += 512) {
            i += g_part[3 * j + 0];
            a += g_part[3 * j + 1];
            b += g_part[3 * j + 2];
        }
        #pragma unroll
        for (int o = 16; o > 0; o >>= 1) {
            i += __shfl_down_sync(0xffffffffu, i, o);
            a += __shfl_down_sync(0xffffffffu, a, o);
            b += __shfl_down_sync(0xffffffffu, b, o);
        }
        __syncthreads();
        if (lane == 0) { red[wid] = i; red[16 + wid] = a; red[32 + wid] = b; }
        __syncthreads();
        if (tid == 0) {
            float I = 0.f, A = 0.f, B = 0.f;
            #pragma unroll
            for (int q = 0; q < 16; q++) { I += red[q]; A += red[16 + q]; B += red[32 + q]; }
            out[0] = 1.f - (2.f * I + 1.f) / (A + B + 1.f);
            g_count = 0;
        }
    }
}

extern "C" void kernel_launch(void* const* d_in, const int* in_sizes, int n_in,
                              void* d_out, int out_size)
{
    const float* input  = (const float*)d_in[0];
    const float* target = (const float*)d_in[1];
    const int nImg = in_sizes[0] / (Hd * Wd);
    const int grid = nImg * (Hd / Rr);              // 256
    const size_t smem = (size_t)RING * Wd * sizeof(__half);   // 65536 B

    cudaFuncSetAttribute(wdice_main,
                         cudaFuncAttributeMaxDynamicSharedMemorySize, (int)smem);
    wdice_main<<<grid, 512, smem>>>(input, target, (float*)d_out);
}